// round 3
// baseline (speedup 1.0000x reference)
#include <cuda_runtime.h>
#include <math.h>

#define BB 8
#define TT 256
#define SS 256
#define HH 512

// Scratch: projected tensors (4 MB each). Device globals — no allocation.
__device__ float g_enc_f[BB * SS * HH];
__device__ float g_qry_f[BB * TT * HH];

// Y[n,o] = sum_h X[n,h] * W[o,h]   (N x H) @ (H x H)^T, both K-major.
// Tile 32x32, 16x16 threads, 2x2 outputs/thread, K-chunk 32.
__global__ void gemm_nt_kernel(const float* __restrict__ X,
                               const float* __restrict__ W,
                               int which_out) {
    __shared__ float Xs[32][33];
    __shared__ float Ws[32][33];
    float* __restrict__ Y = which_out ? g_qry_f : g_enc_f;

    int tx = threadIdx.x, ty = threadIdx.y;
    int tid = ty * 16 + tx;
    int n0 = blockIdx.y * 32;
    int o0 = blockIdx.x * 32;

    float acc00 = 0.f, acc01 = 0.f, acc10 = 0.f, acc11 = 0.f;

    for (int k0 = 0; k0 < HH; k0 += 32) {
        #pragma unroll
        for (int i = 0; i < 4; i++) {
            int idx = tid + i * 256;       // 0..1023
            int r = idx >> 5, c = idx & 31;
            Xs[r][c] = X[(size_t)(n0 + r) * HH + k0 + c];
            Ws[r][c] = W[(size_t)(o0 + r) * HH + k0 + c];
        }
        __syncthreads();
        #pragma unroll
        for (int k = 0; k < 32; k++) {
            float x0 = Xs[ty * 2][k];
            float x1 = Xs[ty * 2 + 1][k];
            float w0 = Ws[tx * 2][k];
            float w1 = Ws[tx * 2 + 1][k];
            acc00 = fmaf(x0, w0, acc00);
            acc01 = fmaf(x0, w1, acc01);
            acc10 = fmaf(x1, w0, acc10);
            acc11 = fmaf(x1, w1, acc11);
        }
        __syncthreads();
    }
    Y[(size_t)(n0 + ty * 2)     * HH + o0 + tx * 2]     = acc00;
    Y[(size_t)(n0 + ty * 2)     * HH + o0 + tx * 2 + 1] = acc01;
    Y[(size_t)(n0 + ty * 2 + 1) * HH + o0 + tx * 2]     = acc10;
    Y[(size_t)(n0 + ty * 2 + 1) * HH + o0 + tx * 2 + 1] = acc11;
}

__device__ __forceinline__ float fast_tanh(float x) {
    float r;
    asm("tanh.approx.f32 %0, %1;" : "=f"(r) : "f"(x));
    return r;
}

// One block per (b, t): scores (masked), softmax, weighted sum — fully fused.
__global__ __launch_bounds__(256)
void attn_kernel(const float* __restrict__ enc,
                 const int* __restrict__ src_len,
                 const float* __restrict__ v,
                 float* __restrict__ out) {
    __shared__ float q_s[HH];
    __shared__ float v_s[HH];
    __shared__ float w_s[SS];     // scores, then softmax weights
    __shared__ float red[256];

    int b = blockIdx.y;
    int t = blockIdx.x;
    int tid = threadIdx.x;
    int lane = tid & 31, warp = tid >> 5;

    for (int h = tid; h < HH; h += 256) {
        q_s[h] = g_qry_f[((size_t)b * TT + t) * HH + h];
        v_s[h] = v[h];
    }
    __syncthreads();

    int len = src_len[b];         // int32! (JAX x64-disabled downcasts int64)

    // ---- scores: each warp owns s = warp, warp+8, ... (skip masked s entirely)
    for (int s = warp; s < len; s += 8) {
        const float* __restrict__ e = g_enc_f + ((size_t)b * SS + s) * HH;
        float acc = 0.f;
        #pragma unroll
        for (int k = 0; k < HH / 32; k++) {
            int h = lane + k * 32;
            float x = e[h] + q_s[h];
            acc = fmaf(v_s[h], fast_tanh(x), acc);
        }
        #pragma unroll
        for (int o = 16; o > 0; o >>= 1)
            acc += __shfl_xor_sync(0xffffffffu, acc, o);
        if (lane == 0) w_s[s] = acc;
    }
    __syncthreads();

    // ---- masked softmax over S (256 threads, 1 score each)
    float val = (tid < len) ? w_s[tid] : -INFINITY;
    red[tid] = val;
    __syncthreads();
    #pragma unroll
    for (int o = 128; o > 0; o >>= 1) {
        if (tid < o) red[tid] = fmaxf(red[tid], red[tid + o]);
        __syncthreads();
    }
    float m = red[0];
    __syncthreads();
    float ex = (tid < len) ? __expf(val - m) : 0.f;
    red[tid] = ex;
    __syncthreads();
    #pragma unroll
    for (int o = 128; o > 0; o >>= 1) {
        if (tid < o) red[tid] += red[tid + o];
        __syncthreads();
    }
    float inv = 1.f / red[0];
    __syncthreads();
    w_s[tid] = ex * inv;
    __syncthreads();

    // ---- attn_out[b,t,h] = sum_{s<len} w_s * enc[b,s,h]
    for (int h = tid; h < HH; h += 256) {
        float acc = 0.f;
        const float* __restrict__ ebase = enc + (size_t)b * SS * HH + h;
        for (int s = 0; s < len; s++)
            acc = fmaf(w_s[s], ebase[(size_t)s * HH], acc);
        out[((size_t)b * TT + t) * HH + h] = acc;
    }
}

extern "C" void kernel_launch(void* const* d_in, const int* in_sizes, int n_in,
                              void* d_out, int out_size) {
    const float* query   = (const float*)d_in[0];
    const float* enc     = (const float*)d_in[1];
    const int*   src_len = (const int*)d_in[2];
    const float* W_h     = (const float*)d_in[3];
    const float* W_s     = (const float*)d_in[4];
    const float* v       = (const float*)d_in[5];
    float*       out     = (float*)d_out;

    dim3 gblk(16, 16);
    dim3 ggrd(HH / 32, (BB * SS) / 32);            // 16 x 64
    gemm_nt_kernel<<<ggrd, gblk>>>(enc,   W_h, 0); // -> g_enc_f
    gemm_nt_kernel<<<ggrd, gblk>>>(query, W_s, 1); // -> g_qry_f

    dim3 agrd(TT, BB);                             // 2048 blocks
    attn_kernel<<<agrd, 256>>>(enc, src_len, v, out);
}

// round 4
// speedup vs baseline: 1.1046x; 1.1046x over previous
#include <cuda_runtime.h>
#include <math.h>

#define BB 8
#define TT 256
#define SS 256
#define HH 512
#define TQ 8

// Scratch: projected tensors (4 MB each). Device globals — no allocation.
__device__ float g_enc_f[BB * SS * HH];
__device__ float g_qry_f[BB * TT * HH];

// ---------------------------------------------------------------------------
// tf32 helpers
// ---------------------------------------------------------------------------
__device__ __forceinline__ unsigned f2tf32(float x) {
    unsigned r;
    asm("cvt.rna.tf32.f32 %0, %1;" : "=r"(r) : "f"(x));
    return r;
}

__device__ __forceinline__ void mma_tf32(float* c, const unsigned* a, const unsigned* b) {
    asm("mma.sync.aligned.m16n8k8.row.col.f32.tf32.tf32.f32 "
        "{%0,%1,%2,%3},{%4,%5,%6,%7},{%8,%9},{%0,%1,%2,%3};"
        : "+f"(c[0]), "+f"(c[1]), "+f"(c[2]), "+f"(c[3])
        : "r"(a[0]), "r"(a[1]), "r"(a[2]), "r"(a[3]), "r"(b[0]), "r"(b[1]));
}

// ---------------------------------------------------------------------------
// Fused projection GEMM (tensor cores, tf32):
//   rows [0,2048):    g_enc_f[n,o] = sum_h enc[n,h]   * W_h[o,h]
//   rows [2048,4096): g_qry_f[n,o] = sum_h query[n,h] * W_s[o,h]
// Block: 256 thr = 8 warps (4m x 2n), block tile 128x64, warp tile 32x32.
// No smem: fragments loaded straight from global (L1/L2 give the reuse).
// ---------------------------------------------------------------------------
__global__ __launch_bounds__(256)
void gemm_tf32_kernel(const float* __restrict__ enc,
                      const float* __restrict__ qry,
                      const float* __restrict__ W_h,
                      const float* __restrict__ W_s) {
    int tid  = threadIdx.x;
    int lane = tid & 31, warp = tid >> 5;
    int g  = lane >> 2;      // groupID 0..7
    int tg = lane & 3;       // thread-in-group 0..3
    int warp_m = warp & 3;   // 0..3
    int warp_n = warp >> 2;  // 0..1

    int m_blk = blockIdx.y * 128;          // global fused-row base
    int n_blk = blockIdx.x * 64;

    const float* X;
    const float* W;
    float*       Y;
    if (m_blk < 2048) {
        X = enc + (size_t)m_blk * HH;
        W = W_h;
        Y = g_enc_f + (size_t)m_blk * HH;
    } else {
        X = qry + (size_t)(m_blk - 2048) * HH;
        W = W_s;
        Y = g_qry_f + (size_t)(m_blk - 2048) * HH;
    }

    int m_base = warp_m * 32;              // local row base within block tile
    int n_base = n_blk + warp_n * 32;      // global col base

    float acc[2][4][4];
    #pragma unroll
    for (int i = 0; i < 2; i++)
        #pragma unroll
        for (int j = 0; j < 4; j++)
            #pragma unroll
            for (int c = 0; c < 4; c++) acc[i][j][c] = 0.f;

    for (int k0 = 0; k0 < HH; k0 += 8) {
        unsigned a[2][4], b[4][2];
        #pragma unroll
        for (int i = 0; i < 2; i++) {
            const float* xp = X + (size_t)(m_base + i * 16 + g) * HH + k0 + tg;
            a[i][0] = f2tf32(xp[0]);
            a[i][1] = f2tf32(xp[8 * HH]);
            a[i][2] = f2tf32(xp[4]);
            a[i][3] = f2tf32(xp[8 * HH + 4]);
        }
        #pragma unroll
        for (int j = 0; j < 4; j++) {
            const float* wp = W + (size_t)(n_base + j * 8 + g) * HH + k0 + tg;
            b[j][0] = f2tf32(wp[0]);
            b[j][1] = f2tf32(wp[4]);
        }
        #pragma unroll
        for (int i = 0; i < 2; i++)
            #pragma unroll
            for (int j = 0; j < 4; j++)
                mma_tf32(acc[i][j], a[i], b[j]);
    }

    // Epilogue: c0:(g, 2tg) c1:(g, 2tg+1) c2:(g+8, 2tg) c3:(g+8, 2tg+1)
    #pragma unroll
    for (int i = 0; i < 2; i++) {
        #pragma unroll
        for (int j = 0; j < 4; j++) {
            int row0 = m_base + i * 16 + g;
            int col  = n_base + j * 8 + 2 * tg;
            Y[(size_t)row0 * HH + col]           = acc[i][j][0];
            Y[(size_t)row0 * HH + col + 1]       = acc[i][j][1];
            Y[(size_t)(row0 + 8) * HH + col]     = acc[i][j][2];
            Y[(size_t)(row0 + 8) * HH + col + 1] = acc[i][j][3];
        }
    }
}

__device__ __forceinline__ float fast_tanh(float x) {
    float r;
    asm("tanh.approx.f32 %0, %1;" : "=f"(r) : "f"(x));
    return r;
}

// ---------------------------------------------------------------------------
// Fused attention, TQ=8 queries per block: scores + softmax + AV.
// Score phase: warp-per-s; the enc_f row is held in registers and reused
// across all 8 queries (8x less L2 traffic than 1-query-per-block).
// ---------------------------------------------------------------------------
__global__ __launch_bounds__(256)
void attn_kernel(const float* __restrict__ enc,
                 const int* __restrict__ src_len,
                 const float* __restrict__ v,
                 float* __restrict__ out) {
    __shared__ float q_s[TQ][HH];   // 16 KB
    __shared__ float v_s[HH];       //  2 KB
    __shared__ float w_s[TQ][SS];   //  8 KB

    int b  = blockIdx.y;
    int t0 = blockIdx.x * TQ;
    int tid = threadIdx.x;
    int lane = tid & 31, warp = tid >> 5;

    // q rows t0..t0+7 are contiguous in g_qry_f -> flat copy
    {
        const float* src = g_qry_f + ((size_t)b * TT + t0) * HH;
        float* dst = &q_s[0][0];
        for (int i = tid; i < TQ * HH; i += 256) dst[i] = src[i];
        for (int h = tid; h < HH; h += 256) v_s[h] = v[h];
    }
    __syncthreads();

    int len = src_len[b];   // int32, in [1, S]

    // ---- scores (skip masked s entirely)
    {
        float vr[16];
        #pragma unroll
        for (int k = 0; k < 16; k++) vr[k] = v_s[lane + 32 * k];

        for (int s = warp; s < len; s += 8) {
            const float* __restrict__ e = g_enc_f + ((size_t)b * SS + s) * HH;
            float er[16];
            #pragma unroll
            for (int k = 0; k < 16; k++) er[k] = e[lane + 32 * k];

            float acc[TQ];
            #pragma unroll
            for (int tq = 0; tq < TQ; tq++) acc[tq] = 0.f;

            #pragma unroll
            for (int k = 0; k < 16; k++) {
                #pragma unroll
                for (int tq = 0; tq < TQ; tq++) {
                    float x = er[k] + q_s[tq][lane + 32 * k];
                    acc[tq] = fmaf(vr[k], fast_tanh(x), acc[tq]);
                }
            }
            #pragma unroll
            for (int tq = 0; tq < TQ; tq++) {
                float a = acc[tq];
                #pragma unroll
                for (int o = 16; o > 0; o >>= 1)
                    a += __shfl_xor_sync(0xffffffffu, a, o);
                if (lane == 0) w_s[tq][s] = a;
            }
        }
    }
    __syncthreads();

    // ---- softmax: warp `warp` owns query row tq = warp (8 warps == TQ)
    {
        int tq = warp;
        float vals[SS / 32];
        float m = -INFINITY;
        #pragma unroll
        for (int j = 0; j < SS / 32; j++) {
            int s = lane + 32 * j;
            float x = (s < len) ? w_s[tq][s] : -INFINITY;
            vals[j] = x;
            m = fmaxf(m, x);
        }
        #pragma unroll
        for (int o = 16; o > 0; o >>= 1)
            m = fmaxf(m, __shfl_xor_sync(0xffffffffu, m, o));
        float sum = 0.f;
        #pragma unroll
        for (int j = 0; j < SS / 32; j++) {
            int s = lane + 32 * j;
            float e = (s < len) ? __expf(vals[j] - m) : 0.f;
            vals[j] = e;
            sum += e;
        }
        #pragma unroll
        for (int o = 16; o > 0; o >>= 1)
            sum += __shfl_xor_sync(0xffffffffu, sum, o);
        float inv = 1.f / sum;
        #pragma unroll
        for (int j = 0; j < SS / 32; j++)
            w_s[tq][lane + 32 * j] = vals[j] * inv;
    }
    __syncthreads();

    // ---- AV: each thread owns h = 2*tid, 2*tid+1 (float2), all 8 queries
    {
        float2 acc[TQ];
        #pragma unroll
        for (int tq = 0; tq < TQ; tq++) acc[tq] = make_float2(0.f, 0.f);

        const float2* __restrict__ eb =
            (const float2*)(enc + (size_t)b * SS * HH) + tid;
        for (int s = 0; s < len; s++) {
            float2 ev = eb[(size_t)s * (HH / 2)];
            #pragma unroll
            for (int tq = 0; tq < TQ; tq++) {
                float w = w_s[tq][s];
                acc[tq].x = fmaf(w, ev.x, acc[tq].x);
                acc[tq].y = fmaf(w, ev.y, acc[tq].y);
            }
        }
        #pragma unroll
        for (int tq = 0; tq < TQ; tq++) {
            float2* op = (float2*)(out + ((size_t)b * TT + t0 + tq) * HH) + tid;
            *op = acc[tq];
        }
    }
}

extern "C" void kernel_launch(void* const* d_in, const int* in_sizes, int n_in,
                              void* d_out, int out_size) {
    const float* query   = (const float*)d_in[0];
    const float* enc     = (const float*)d_in[1];
    const int*   src_len = (const int*)d_in[2];
    const float* W_h     = (const float*)d_in[3];
    const float* W_s     = (const float*)d_in[4];
    const float* v       = (const float*)d_in[5];
    float*       out     = (float*)d_out;

    dim3 ggrd(HH / 64, (2 * BB * SS) / 128);   // (8, 32) = 256 blocks
    gemm_tf32_kernel<<<ggrd, 256>>>(enc, query, W_h, W_s);

    dim3 agrd(TT / TQ, BB);                    // (32, 8) = 256 blocks
    attn_kernel<<<agrd, 256>>>(enc, src_len, v, out);
}